// round 9
// baseline (speedup 1.0000x reference)
#include <cuda_runtime.h>
#include <cstdint>
#include <math.h>

#define T      1024
#define LRC    0.01f

// Scratch (device globals — allocation is forbidden)
__device__ float g_cw[16 * T];                 // control weights [rs, n]
__device__ float g_epart[32];                  // 8 cluster ranks x 4 e partials
__device__ unsigned long long g_acc64[4096];   // fixed-point out accumulators
__device__ unsigned int g_cnt[4096];           // per-element arrival counters

// ---------------------------------------------------------------------------
// k1 (8-CTA cluster, 256 thr/CTA): fused err + cw + gamma.
// Fires the PDL trigger immediately so k2 can start staging Fx in parallel.
// ---------------------------------------------------------------------------
__global__ void __cluster_dims__(8, 1, 1) k1(const float* __restrict__ Fx,
                                             const float* __restrict__ Dis,
                                             const float* __restrict__ w0,
                                             float* __restrict__ out) {
    asm volatile("griddepcontrol.launch_dependents;");

    const int tid  = threadIdx.x;
    const int rank = blockIdx.x;
    const float4* w4  = (const float4*)w0;
    const float4* fx4 = (const float4*)Fx;

    // ---- phase A: partial err dot products over this CTA's slice ----
    float acc[4] = {0.f, 0.f, 0.f, 0.f};
#pragma unroll
    for (int s = 0; s < 2; s++) {
        const int i4 = rank * 512 + s * 256 + tid;    // float4 index into w0
        const float4 w = w4[i4];
        const int rs = i4 >> 8, n4 = i4 & 255;
#pragma unroll
        for (int e = 0; e < 4; e++) {
            const float4 x = fx4[(rs << 10) + (e << 8) + n4];
            acc[e] += x.x * w.x + x.y * w.y + x.z * w.z + x.w * w.w;
        }
    }
#pragma unroll
    for (int o = 16; o; o >>= 1)
#pragma unroll
        for (int e = 0; e < 4; e++) acc[e] += __shfl_xor_sync(0xffffffffu, acc[e], o);

    __shared__ float sp[8][4];
    __shared__ float serr[4];
    if ((tid & 31) == 0)
#pragma unroll
        for (int e = 0; e < 4; e++) sp[tid >> 5][e] = acc[e];
    __syncthreads();
    if (tid < 4) {
        float s = 0.f;
#pragma unroll
        for (int wq = 0; wq < 8; wq++) s += sp[wq][tid];
        g_epart[rank * 4 + tid] = s;
    }

    asm volatile("barrier.cluster.arrive.release.aligned;" ::: "memory");

    // ---- barrier gap: gamma vector (independent work) ----
    {
        const int g = rank * 256 + tid;               // 0..2047
        if (g < 1024)
            out[4096 + g] = __expf((float)(1023 - g) * -1.0005003e-3f);
    }

    asm volatile("barrier.cluster.wait.acquire.aligned;" ::: "memory");

    if (tid < 4) {
        volatile const float* gp = g_epart;
        float s = 0.f;
#pragma unroll
        for (int r = 0; r < 8; r++) s += gp[r * 4 + tid];
        serr[tid] = Dis[tid * T + (T - 1)] - s;
    }
    __syncthreads();
    const float e0 = serr[0], e1 = serr[1], e2 = serr[2], e3 = serr[3];

    // ---- phase B: cw over the same slice (Fx/w0 L1-hot) ----
    float4* cw4 = (float4*)g_cw;
#pragma unroll
    for (int s = 0; s < 2; s++) {
        const int i4 = rank * 512 + s * 256 + tid;
        float4 c = w4[i4];
        const int rs = i4 >> 8, n4 = i4 & 255;
        const float4 x0 = fx4[(rs << 10) + (0 << 8) + n4];
        const float4 x1 = fx4[(rs << 10) + (1 << 8) + n4];
        const float4 x2 = fx4[(rs << 10) + (2 << 8) + n4];
        const float4 x3 = fx4[(rs << 10) + (3 << 8) + n4];
        c.x += LRC * (x0.x * e0 + x1.x * e1 + x2.x * e2 + x3.x * e3);
        c.y += LRC * (x0.y * e0 + x1.y * e1 + x2.y * e2 + x3.y * e3);
        c.z += LRC * (x0.z * e0 + x1.z * e1 + x2.z * e2 + x3.z * e3);
        c.w += LRC * (x0.w * e0 + x1.w * e1 + x2.w * e2 + x3.w * e3);
        cw4[i4] = c;
    }
}

// ---------------------------------------------------------------------------
// k2: causal correlation. grid (32 pair-tiles, 4 e, 4 rs-quarters), 544 thr,
// 33 KB smem, __launch_bounds__(544,3) -> 3 CTAs/SM = 51 warps/SM.
// Low-register tile: thread owns 8 t's x 4 n (acc8, 12-float window).
// The 4 quarter-partials per out element combine via FIXED-POINT int64
// atomicAdd (integer addition commutes -> bitwise deterministic); the 4th
// arriver (elected by a counter) converts to float and resets the scratch.
// ---------------------------------------------------------------------------
#define SFQ   1048            // sF row stride in floats (20 pad + 1024 + 4 tail)
#define NF4   262             // float4 per sF row
#define SWQ   (4 * SFQ)       // 4192: start of cw rows (4 rows of 1024)
#define FPSCALE   16777216.0f             // 2^24
#define FPINV     5.9604644775390625e-8f  // 2^-24

extern __shared__ float smem[];

__global__ void __launch_bounds__(544, 3)
k2(const float* __restrict__ Fx, float* __restrict__ out) {
    const int tid = threadIdx.x;
    const int b   = blockIdx.x;
    const int e   = blockIdx.y;
    const int q   = blockIdx.z;                     // rs quarter (4 rows)
    const int t0A = b << 4, t0B = (63 - b) << 4;
    const int cA = (t0A + 16) >> 2;                 // 4..128 chunks for tile A
    const int cB = 260 - cA;                        // chunks for tile B

    const float4 z4 = make_float4(0.f, 0.f, 0.f, 0.f);

    // ---- stage this quarter's 4 Fx rows (front zero-padded) ----
    float4* dF = (float4*)smem;
    for (int idx = tid; idx < 4 * NF4; idx += 544) {
        const int qq = idx / NF4, i = idx - qq * NF4;
        const int rs = (q << 2) + qq;
        float4 v = z4;
        if (i >= 5 && i < 261)
            v = ((const float4*)Fx)[(((rs << 2) + e) << 8) + i - 5];
        dF[qq * NF4 + i] = v;
    }

    // ---- wait for k1's g_cw, then stage this quarter's 4 cw rows ----
    asm volatile("griddepcontrol.wait;" ::: "memory");
    float4* dW = (float4*)(smem + SWQ);
    const float4* ws = (const float4*)(g_cw + (q << 12));
    for (int idx = tid; idx < 1024; idx += 544)
        dW[idx] = ws[idx];
    __syncthreads();

    // ---- compute: 8 t's x 4 n per thread over 4 rs rows ----
    const int h    = (tid >= 260);                  // t-half of the 16-tile
    const int c    = tid - (h ? 260 : 0);           // chunk id 0..259
    const bool active = (tid < 520);
    const bool isA = (c < cA);
    const int t0   = isA ? t0A : t0B;
    const int cc   = isA ? c : (c - cA);            // chunk within tile
    const int nb   = cc << 2;
    const int tbase = t0 + (h << 3);
    const int ab   = 16 + tbase - nb;               // aligned window base

    float acc[8];
#pragma unroll
    for (int j = 0; j < 8; j++) acc[j] = 0.f;

    if (active) {
#pragma unroll
        for (int qq = 0; qq < 4; qq++) {
            const float4 w = *(const float4*)&smem[SWQ + (qq << 10) + nb];
            const float4* F4 = (const float4*)&smem[qq * SFQ + ab];
            float ff[12];
#pragma unroll
            for (int m = 0; m < 3; m++) {
                const float4 v = F4[m];
                ff[4 * m + 0] = v.x; ff[4 * m + 1] = v.y;
                ff[4 * m + 2] = v.z; ff[4 * m + 3] = v.w;
            }
#pragma unroll
            for (int j = 0; j < 8; j++)
                acc[j] += ff[4 + j] * w.x + ff[3 + j] * w.y
                        + ff[2 + j] * w.z + ff[1 + j] * w.w;
        }
    }
    __syncthreads();

    // ---- per-chunk partials overlay the staging buffer ----
    // rows 0..15 (tile A): [16][128] at 0; rows 16..31 (tile B): [16][256] at 2048
    if (active) {
        if (isA) {
#pragma unroll
            for (int j = 0; j < 8; j++)
                smem[((h << 3) + j) * 128 + cc] = acc[j];
        } else {
#pragma unroll
            for (int j = 0; j < 8; j++)
                smem[2048 + ((h << 3) + j) * 256 + cc] = acc[j];
        }
    }
    __syncthreads();

    // ---- reduce: 32 rows x 16 lanes, shuffle within 16-lane groups ----
    if (tid < 512) {
        const int row = tid >> 4, k = tid & 15;
        float s = 0.f;
        if (row < 16) {
            for (int c2 = k; c2 < cA; c2 += 16) s += smem[row * 128 + c2];
        } else {
            const int r2 = row - 16;
            for (int c2 = k; c2 < cB; c2 += 16) s += smem[2048 + r2 * 256 + c2];
        }
#pragma unroll
        for (int o = 8; o; o >>= 1) s += __shfl_xor_sync(0xffffffffu, s, o);

        if (k == 0) {
            const int t = (row < 16) ? (t0A + row) : (t0B + row - 16);
            const int i = (t << 2) + e;
            const long long ll = llrintf(s * FPSCALE);
            atomicAdd(&g_acc64[i], (unsigned long long)ll);
            __threadfence();
            const unsigned int old = atomicAdd(&g_cnt[i], 1u);
            if (old == 3u) {                // last arriver converts + resets
                __threadfence();
                const unsigned long long v = atomicExch(&g_acc64[i], 0ull);
                g_cnt[i] = 0u;
                out[i] = (float)(long long)v * FPINV;
            }
        }
    }
}

// ---------------------------------------------------------------------------
extern "C" void kernel_launch(void* const* d_in, const int* in_sizes, int n_in,
                              void* d_out, int out_size) {
    const float* Fx  = (const float*)d_in[0];   // [4,4,4,1024]
    const float* Dis = (const float*)d_in[1];   // [4,1024]
    const float* w0  = (const float*)d_in[2];   // [4,4,1024]
    float* out = (float*)d_out;                 // [1024*4 anti | 1024 gamma]

    k1<<<8, 256>>>(Fx, Dis, w0, out);

    // k2 with programmatic dependent launch (overlaps with k1)
    const size_t dynBytes = (size_t)(SWQ + 4 * 1024) * sizeof(float); // 33,152
    cudaLaunchConfig_t cfg = {};
    cfg.gridDim = dim3(32, 4, 4);
    cfg.blockDim = dim3(544);
    cfg.dynamicSmemBytes = dynBytes;
    cfg.stream = 0;
    cudaLaunchAttribute attr[1];
    attr[0].id = cudaLaunchAttributeProgrammaticStreamSerialization;
    attr[0].val.programmaticStreamSerializationAllowed = 1;
    cfg.attrs = attr;
    cfg.numAttrs = 1;
    cudaLaunchKernelEx(&cfg, k2, Fx, out);
}

// round 11
// speedup vs baseline: 1.3400x; 1.3400x over previous
#include <cuda_runtime.h>
#include <cstdint>
#include <math.h>

#define T      1024
#define LRC    0.01f

// Scratch (device globals — allocation is forbidden)
__device__ float g_cw[16 * T];      // control weights [rs, n]
__device__ float g_epart[32];       // 8 cluster ranks x 4 e partials

// ---------------------------------------------------------------------------
// k1 (8-CTA cluster, 256 thr/CTA): fused err + cw + gamma + out zero-init.
// Fires the PDL trigger immediately so k2 can start staging Fx in parallel.
// gamma/zero work hides in the cluster-barrier gap.
// ---------------------------------------------------------------------------
__global__ void __cluster_dims__(8, 1, 1) k1(const float* __restrict__ Fx,
                                             const float* __restrict__ Dis,
                                             const float* __restrict__ w0,
                                             float* __restrict__ out) {
    asm volatile("griddepcontrol.launch_dependents;");

    const int tid  = threadIdx.x;
    const int rank = blockIdx.x;
    const float4* w4  = (const float4*)w0;
    const float4* fx4 = (const float4*)Fx;

    // ---- phase A: partial err dot products over this CTA's slice ----
    float acc[4] = {0.f, 0.f, 0.f, 0.f};
#pragma unroll
    for (int s = 0; s < 2; s++) {
        const int i4 = rank * 512 + s * 256 + tid;    // float4 index into w0
        const float4 w = w4[i4];
        const int rs = i4 >> 8, n4 = i4 & 255;
#pragma unroll
        for (int e = 0; e < 4; e++) {
            const float4 x = fx4[(rs << 10) + (e << 8) + n4];
            acc[e] += x.x * w.x + x.y * w.y + x.z * w.z + x.w * w.w;
        }
    }
#pragma unroll
    for (int o = 16; o; o >>= 1)
#pragma unroll
        for (int e = 0; e < 4; e++) acc[e] += __shfl_xor_sync(0xffffffffu, acc[e], o);

    __shared__ float sp[8][4];
    __shared__ float serr[4];
    if ((tid & 31) == 0)
#pragma unroll
        for (int e = 0; e < 4; e++) sp[tid >> 5][e] = acc[e];
    __syncthreads();
    if (tid < 4) {
        float s = 0.f;
#pragma unroll
        for (int wq = 0; wq < 8; wq++) s += sp[wq][tid];
        g_epart[rank * 4 + tid] = s;
    }

    asm volatile("barrier.cluster.arrive.release.aligned;" ::: "memory");

    // ---- barrier gap: zero out[0:4096) + gamma vector (independent work) ----
    {
        const int g = rank * 256 + tid;               // 0..2047
        if (g < 1024) {
            ((float4*)out)[g] = make_float4(0.f, 0.f, 0.f, 0.f);
            out[4096 + g] = __expf((float)(1023 - g) * -1.0005003e-3f);
        }
    }

    asm volatile("barrier.cluster.wait.acquire.aligned;" ::: "memory");

    if (tid < 4) {
        volatile const float* gp = g_epart;
        float s = 0.f;
#pragma unroll
        for (int r = 0; r < 8; r++) s += gp[r * 4 + tid];
        serr[tid] = Dis[tid * T + (T - 1)] - s;
    }
    __syncthreads();
    const float e0 = serr[0], e1 = serr[1], e2 = serr[2], e3 = serr[3];

    // ---- phase B: cw over the same slice (Fx/w0 L1-hot) ----
    float4* cw4 = (float4*)g_cw;
#pragma unroll
    for (int s = 0; s < 2; s++) {
        const int i4 = rank * 512 + s * 256 + tid;
        float4 c = w4[i4];
        const int rs = i4 >> 8, n4 = i4 & 255;
        const float4 x0 = fx4[(rs << 10) + (0 << 8) + n4];
        const float4 x1 = fx4[(rs << 10) + (1 << 8) + n4];
        const float4 x2 = fx4[(rs << 10) + (2 << 8) + n4];
        const float4 x3 = fx4[(rs << 10) + (3 << 8) + n4];
        c.x += LRC * (x0.x * e0 + x1.x * e1 + x2.x * e2 + x3.x * e3);
        c.y += LRC * (x0.y * e0 + x1.y * e1 + x2.y * e2 + x3.y * e3);
        c.z += LRC * (x0.z * e0 + x1.z * e1 + x2.z * e2 + x3.z * e3);
        c.w += LRC * (x0.w * e0 + x1.w * e1 + x2.w * e2 + x3.w * e3);
        cw4[i4] = c;
    }
}

// ---------------------------------------------------------------------------
// k2: causal correlation. grid (32 pair-tiles, 4 e, 2 rs-halves) = 256 CTAs,
// 640 thr, 2 CTAs/SM, ONE wave. Sub-groups of 320 threads split the half's
// 8 rs rows (4 each). cw is NOT staged: read via __ldg float4 (L2/L1-hot),
// so the PDL wait sits directly before compute and Fx staging overlaps k1.
// Reduction: partials -> smem overlay -> 32 rows x 16 lanes + shuffle ->
// float atomicAdd (exactly 2 contributors per element -> deterministic).
// Dyn smem = max(staging 8*SFQ, reduction 2*RSEG) = 2*RSEG floats.
// ---------------------------------------------------------------------------
#define SFQ   1048            // sF row stride in floats (20 pad + 1024 + 4 tail)
#define NF4   262             // float4 per sF row
#define RSEG  6144            // reduction floats per sub-group (16*128+16*256)

extern __shared__ float smem[];

__global__ void __launch_bounds__(640, 2)
k2(const float* __restrict__ Fx, float* __restrict__ out) {
    const int tid  = threadIdx.x;
    const int b    = blockIdx.x;
    const int e    = blockIdx.y;
    const int half = blockIdx.z;                    // rs-half
    const int sub  = (tid >= 320);                  // qq sub-group
    const int tloc = tid - (sub << 8) - (sub << 6); // tid - sub*320
    const int t0A = b << 4, t0B = (63 - b) << 4;
    const int cA = (t0A + 16) >> 2;                 // 4..128 chunks for tile A
    const int cB = 260 - cA;                        // chunks for tile B
    const bool active = tloc < 260;
    const bool isA = tloc < cA;
    const int t0 = isA ? t0A : t0B;
    const int nb = (isA ? tloc : (tloc - cA)) << 2; // n-chunk base
    const int ab = 16 + t0 - nb;                    // aligned sF read base

    const float4 z4 = make_float4(0.f, 0.f, 0.f, 0.f);

    // ---- stage this half's 8 Fx rows (front zero-padded) — k1-independent ----
    float4* dF = (float4*)smem;
    for (int idx = tid; idx < 8 * NF4; idx += 640) {
        const int qq = idx / NF4, i = idx - qq * NF4;
        const int rs = (half << 3) + qq;
        float4 v = z4;
        if (i >= 5 && i < 261)
            v = ((const float4*)Fx)[(((rs << 2) + e) << 8) + i - 5];
        dF[qq * NF4 + i] = v;
    }
    __syncthreads();

    // ---- wait for k1 (g_cw + out zero-init), then compute directly ----
    asm volatile("griddepcontrol.wait;" ::: "memory");

    // ---- compute: 4 rs rows per thread; cw straight from L2/L1 via LDG ----
    float acc[16];
#pragma unroll
    for (int j = 0; j < 16; j++) acc[j] = 0.f;

    if (active) {
        const float4* wG = (const float4*)
            (g_cw + (((half << 3) + (sub << 2)) << 10) + nb); // row stride 1024
        const float* fBase = &smem[(sub << 2) * SFQ + ab];
#pragma unroll
        for (int qq = 0; qq < 4; qq++) {
            const float4 w = __ldg(wG + (qq << 8));           // (qq*1024)/4
            const float4* F4 = (const float4*)(fBase + qq * SFQ);
            float ff[24];
#pragma unroll
            for (int m = 0; m < 6; m++) {
                const float4 v = F4[m];
                ff[4 * m + 0] = v.x; ff[4 * m + 1] = v.y;
                ff[4 * m + 2] = v.z; ff[4 * m + 3] = v.w;
            }
#pragma unroll
            for (int j = 0; j < 16; j++)
                acc[j] += ff[4 + j] * w.x + ff[3 + j] * w.y
                        + ff[2 + j] * w.z + ff[1 + j] * w.w;
        }
    }
    __syncthreads();

    // ---- per-chunk partials overlay the staging buffer ----
    // per sub-group: [16][128] (tile A) then [16][256] (tile B)
    float* redA = smem + sub * RSEG;
    float* redB = redA + 16 * 128;
    if (active) {
        if (isA) {
#pragma unroll
            for (int j = 0; j < 16; j++) redA[j * 128 + tloc] = acc[j];
        } else {
#pragma unroll
            for (int j = 0; j < 16; j++) redB[j * 256 + (tloc - cA)] = acc[j];
        }
    }
    __syncthreads();

    // ---- reduce: 32 rows x 16 lanes, shuffle within 16-lane groups ----
    if (tid < 512) {
        const int row = tid >> 4, k = tid & 15;
        float s = 0.f;
        if (row < 16) {
            for (int c = k; c < cA; c += 16)
                s += smem[row * 128 + c] + smem[RSEG + row * 128 + c];
        } else {
            const int r2 = row - 16;
            for (int c = k; c < cB; c += 16)
                s += smem[2048 + r2 * 256 + c] + smem[RSEG + 2048 + r2 * 256 + c];
        }
#pragma unroll
        for (int o = 8; o; o >>= 1) s += __shfl_xor_sync(0xffffffffu, s, o);

        if (k == 0) {
            const int t = (row < 16) ? (t0A + row) : (t0B + row - 16);
            atomicAdd(&out[(t << 2) + e], s);   // 2 contributors: deterministic
        }
    }
}

// ---------------------------------------------------------------------------
extern "C" void kernel_launch(void* const* d_in, const int* in_sizes, int n_in,
                              void* d_out, int out_size) {
    const float* Fx  = (const float*)d_in[0];   // [4,4,4,1024]
    const float* Dis = (const float*)d_in[1];   // [4,1024]
    const float* w0  = (const float*)d_in[2];   // [4,4,1024]
    float* out = (float*)d_out;                 // [1024*4 anti | 1024 gamma]

    k1<<<8, 256>>>(Fx, Dis, w0, out);

    // k2 with programmatic dependent launch (overlaps with k1)
    const size_t dynBytes = (size_t)(2 * RSEG) * sizeof(float);  // 49,152 B
    cudaLaunchConfig_t cfg = {};
    cfg.gridDim = dim3(32, 4, 2);
    cfg.blockDim = dim3(640);
    cfg.dynamicSmemBytes = dynBytes;
    cfg.stream = 0;
    cudaLaunchAttribute attr[1];
    attr[0].id = cudaLaunchAttributeProgrammaticStreamSerialization;
    attr[0].val.programmaticStreamSerializationAllowed = 1;
    cfg.attrs = attr;
    cfg.numAttrs = 1;
    cudaLaunchKernelEx(&cfg, k2, Fx, out);
}